// round 15
// baseline (speedup 1.0000x reference)
#include <cuda_runtime.h>
#include <cuda_bf16.h>
#include <cuda_fp16.h>
#include <math_constants.h>
#include <cstdint>

// Problem constants
#define BATCH 4
#define SEQ   2048
#define DIM   1024
#define HEADS 16
#define HD    64
#define NROWS (BATCH * SEQ)   // 8192
#define QK_SCALE 0.125f

__device__ __forceinline__ uint32_t smem_u32(const void* p) {
    uint32_t a;
    asm("{ .reg .u64 t; cvta.to.shared.u64 t, %1; cvt.u32.u64 %0, t; }" : "=r"(a) : "l"(p));
    return a;
}
__device__ __forceinline__ void mma16816h(float* d, const uint32_t* a, const uint32_t* b) {
    asm volatile("mma.sync.aligned.m16n8k16.row.col.f32.f16.f16.f32 "
        "{%0,%1,%2,%3}, {%4,%5,%6,%7}, {%8,%9}, {%0,%1,%2,%3};"
        : "+f"(d[0]), "+f"(d[1]), "+f"(d[2]), "+f"(d[3])
        : "r"(a[0]), "r"(a[1]), "r"(a[2]), "r"(a[3]), "r"(b[0]), "r"(b[1]));
}
__device__ __forceinline__ void ldsm_x4(uint32_t* r, uint32_t addr) {
    asm volatile("ldmatrix.sync.aligned.m8n8.x4.shared.b16 {%0,%1,%2,%3}, [%4];"
        : "=r"(r[0]), "=r"(r[1]), "=r"(r[2]), "=r"(r[3]) : "r"(addr));
}
__device__ __forceinline__ void ldsm_x4t(uint32_t* r, uint32_t addr) {
    asm volatile("ldmatrix.sync.aligned.m8n8.x4.trans.shared.b16 {%0,%1,%2,%3}, [%4];"
        : "=r"(r[0]), "=r"(r[1]), "=r"(r[2]), "=r"(r[3]) : "r"(addr));
}
__device__ __forceinline__ void cpa16(uint32_t s, const void* g) {
    asm volatile("cp.async.cg.shared.global [%0], [%1], 16;" :: "r"(s), "l"(g));
}

// ---------------------------------------------------------------------------
// Scratch (all single fp16)
// ---------------------------------------------------------------------------
#define QKV_ELEMS (BATCH * HEADS * SEQ * HD)
__device__ __half g_q16[QKV_ELEMS];         // Q fp16 (pre-scaled)
__device__ __half g_k16[QKV_ELEMS];         // K fp16, compacted along S
__device__ __half g_v16[QKV_ELEMS];         // V fp16, compacted along S
__device__ __half g_x16[NROWS * DIM];       // x fp16
__device__ __half g_w16[4 * DIM * DIM];     // fp16-rounded weights
__device__ __half g_o16[NROWS * DIM];       // attn out fp16
__device__ int g_gather[BATCH * SEQ];
__device__ int g_cnt[BATCH];

// ---------------------------------------------------------------------------
// fp32 -> fp16 round: x and all four weights in ONE launch
// ---------------------------------------------------------------------------
struct h4 { __half v[4]; };

#define N4X (NROWS * DIM / 4)      // 2097152
#define N4W ((DIM * DIM) / 4)      // 262144

__global__ void round_all_kernel(const float* __restrict__ x,
                                 const float* __restrict__ w0, const float* __restrict__ w1,
                                 const float* __restrict__ w2, const float* __restrict__ w3,
                                 __half* __restrict__ dx, __half* __restrict__ dw)
{
    const int total = N4X + 4 * N4W;
    for (int i = blockIdx.x * blockDim.x + threadIdx.x; i < total;
         i += gridDim.x * blockDim.x) {
        const float* s;
        h4* d;
        int j;
        if (i < N4X) {
            s = x; d = (h4*)dx; j = i;
        } else {
            const int k = i - N4X;
            const int w = k / N4W;
            j = k - w * N4W;
            s = (w == 0) ? w0 : (w == 1) ? w1 : (w == 2) ? w2 : w3;
            d = (h4*)dw + (size_t)w * N4W;
        }
        float4 v = ((const float4*)s)[j];
        h4 h;
        h.v[0] = __float2half_rn(v.x); h.v[1] = __float2half_rn(v.y);
        h.v[2] = __float2half_rn(v.z); h.v[3] = __float2half_rn(v.w);
        d[j] = h;
    }
}

// ---------------------------------------------------------------------------
// Mask compaction: stable scan; gather list + count.
// ---------------------------------------------------------------------------
__global__ __launch_bounds__(256)
void compact_kernel(const int* __restrict__ mask,
                    int* __restrict__ gather, int* __restrict__ cnt)
{
    __shared__ int cnts[256];
    __shared__ int offs[256];
    const int b = blockIdx.x;
    const int t = threadIdx.x;
    const int* m = mask + b * SEQ;

    int c = 0;
#pragma unroll
    for (int j = 0; j < 8; j++) c += (m[t * 8 + j] == 0);
    cnts[t] = c;
    __syncthreads();
    if (t == 0) {
        int run = 0;
        for (int i = 0; i < 256; i++) { offs[i] = run; run += cnts[i]; }
        cnt[b] = run;
    }
    __syncthreads();
    int o = offs[t];
#pragma unroll
    for (int j = 0; j < 8; j++) {
        const int s = t * 8 + j;
        if (m[s] == 0) { gather[b * SEQ + o] = s; o++; }
    }
}

// ---------------------------------------------------------------------------
// fp16 single-term GEMM, 512 threads (16 warps, 4x4, 32x32 warp tiles),
// 4-stage cp.async pipeline with STRICT one-group-per-iteration cadence
// (empty commit groups at the tail — the R6..R14 tail race is fixed here).
// mode 0: fp16 scatter [B,H,S,HD] by s (Q, scaled)
// mode 2: A rows gathered; fp16 store at compacted row (K/V)
// mode 1: fp32 row-major
// ---------------------------------------------------------------------------
#define BM 128
#define BN 128
#define BK 32
#define NKC (DIM / BK)
#define TILE_SB (128 * 80)          // 10240 B
#define STAGE_SB (2 * TILE_SB)      // 20480 B: A, W
#define NSTG 4
#define GEMM_SMEM (NSTG * STAGE_SB) // 81920 B
#define GTHREADS 512

__device__ __forceinline__ void gemm_body(
    const __half* A16, const __half* W16,
    const float* bias, float* C, __half* Ch,
    const int* gather, const int* cntp,
    int mode, float scale, int row0, int col0)
{
    extern __shared__ char smraw[];
    const uint32_t smem_base = smem_u32(smraw);

    const int tid = threadIdx.x;
    const int lane = tid & 31;
    const int wid = tid >> 5;        // 0..15
    const int wm = wid & 3;
    const int wn = wid >> 2;

    int cntb = 0;
    if (mode == 2) {
        const int b = row0 >> 11;
        cntb = cntp[b];
        if ((row0 & (SEQ - 1)) >= cntb) return;
    }

    float acc[2][4][4];
#pragma unroll
    for (int i = 0; i < 2; i++)
#pragma unroll
        for (int j = 0; j < 4; j++)
#pragma unroll
            for (int r = 0; r < 4; r++) acc[i][j][r] = 0.f;

    const int r0l = tid >> 2;        // 0..127
    const int cu  = tid & 3;

    const uint4* ap;
    const uint4* wp;
    {
        int srcA;
        if (mode == 2) {
            const int n = row0 + r0l;
            const int b = n >> 11;
            int i = n & (SEQ - 1);
            if (i >= cntb) i = cntb - 1;
            srcA = (b << 11) + gather[(b << 11) + i];
        } else {
            srcA = row0 + r0l;
        }
        ap = (const uint4*)A16 + (size_t)srcA * 128 + cu;
        wp = (const uint4*)W16 + (size_t)(col0 + r0l) * 128 + cu;
    }

#define G_ISSUE(kc, buf) do { \
    uint32_t sb_ = smem_base + (buf) * STAGE_SB; \
    const uint32_t so_ = r0l * 80 + cu * 16; \
    cpa16(sb_ + 0 * TILE_SB + so_, ap + (kc) * 4); \
    cpa16(sb_ + 1 * TILE_SB + so_, wp + (kc) * 4); \
    asm volatile("cp.async.commit_group;" ::: "memory"); \
} while (0)
#define G_EMPTY() asm volatile("cp.async.commit_group;" ::: "memory")

    G_ISSUE(0, 0);
    G_ISSUE(1, 1);
    G_ISSUE(2, 2);

    for (int kc = 0; kc < NKC; kc++) {
        const int buf = kc & 3;
        asm volatile("cp.async.wait_group 2;" ::: "memory");
        __syncthreads();
        // One group per iteration ALWAYS, so "wait_group 2" above guarantees
        // chunk kc is resident even at the pipeline tail.
        if (kc + 3 < NKC) G_ISSUE(kc + 3, (kc + 3) & 3);
        else              G_EMPTY();

        const uint32_t sb = smem_base + buf * STAGE_SB;
#pragma unroll
        for (int s = 0; s < 2; s++) {
            uint32_t a_f[2][4];
            const uint32_t acol = s * 32 + ((lane >> 4) << 4);
#pragma unroll
            for (int mt = 0; mt < 2; mt++) {
                const int r = wm * 32 + mt * 16 + (lane & 15);
                ldsm_x4(a_f[mt], sb + r * 80 + acol);
            }
            uint32_t wf[4][2];
            const int mat = lane >> 3;
            const int mr = lane & 7;
            const uint32_t bcol = s * 32 + ((mat & 1) << 4);
#pragma unroll
            for (int np = 0; np < 2; np++) {
                const int n = wn * 32 + (np * 2 + (mat >> 1)) * 8 + mr;
                uint32_t addr = sb + TILE_SB + n * 80 + bcol;
                uint32_t q[4];
                ldsm_x4(q, addr);
                wf[np * 2][0] = q[0]; wf[np * 2][1] = q[1];
                wf[np * 2 + 1][0] = q[2]; wf[np * 2 + 1][1] = q[3];
            }
#pragma unroll
            for (int mt = 0; mt < 2; mt++)
#pragma unroll
                for (int nt = 0; nt < 4; nt++)
                    mma16816h(acc[mt][nt], a_f[mt], wf[nt]);
        }
    }

    const int g = lane >> 2;
    const int tg2 = (lane & 3) * 2;
#pragma unroll
    for (int mt = 0; mt < 2; mt++) {
#pragma unroll
        for (int hh = 0; hh < 2; hh++) {
            const int n = row0 + wm * 32 + mt * 16 + g + hh * 8;
            if (mode == 1) {
#pragma unroll
                for (int nt = 0; nt < 4; nt++) {
                    const int m = col0 + wn * 32 + nt * 8 + tg2;
                    float2 w;
                    w.x = acc[mt][nt][hh * 2 + 0] + bias[m];
                    w.y = acc[mt][nt][hh * 2 + 1] + bias[m + 1];
                    *(float2*)&C[(size_t)n * DIM + m] = w;
                }
            } else {
                const int b = n >> 11;
                const int sq = n & (SEQ - 1);
                if (mode == 2 && sq >= cntb) continue;
#pragma unroll
                for (int nt = 0; nt < 4; nt++) {
                    const int m = col0 + wn * 32 + nt * 8 + tg2;
                    const float v0 = (acc[mt][nt][hh * 2 + 0] + bias[m]) * scale;
                    const float v1 = (acc[mt][nt][hh * 2 + 1] + bias[m + 1]) * scale;
                    const int h = m >> 6;
                    const int hd = m & (HD - 1);
                    const size_t o = (((size_t)(b * HEADS + h) * SEQ) + sq) * HD + hd;
                    __half2 hv = __floats2half2_rn(v0, v1);
                    *(uint32_t*)&Ch[o] = *reinterpret_cast<uint32_t*>(&hv);
                }
            }
        }
    }
}

// Fused Q/K/V projection: grid (24, 64)
__global__ __launch_bounds__(GTHREADS, 1)
void gemm_qkv(const __half* __restrict__ x16, const __half* __restrict__ w16,
              const float* __restrict__ bq, const float* __restrict__ bk,
              const float* __restrict__ bv,
              const int* __restrict__ gather, const int* __restrict__ cnt,
              __half* __restrict__ q16, __half* __restrict__ k16,
              __half* __restrict__ v16)
{
    const int w = blockIdx.x >> 3;
    const int col0 = (blockIdx.x & 7) * BN;
    const int row0 = blockIdx.y * BM;
    const int NW = DIM * DIM;
    const float* bias = (w == 0) ? bq : (w == 1) ? bk : bv;
    __half* Ch = (w == 0) ? q16 : (w == 1) ? k16 : v16;
    const float scale = (w == 0) ? QK_SCALE : 1.0f;
    const int mode = (w == 0) ? 0 : 2;
    gemm_body(x16, w16 + (size_t)w * NW, bias, nullptr, Ch,
              gather, cnt, mode, scale, row0, col0);
}

__global__ __launch_bounds__(GTHREADS, 1)
void gemm_out(const __half* __restrict__ o16, const __half* __restrict__ w16,
              const float* __restrict__ bias, float* __restrict__ out)
{
    gemm_body(o16, w16, bias, out, nullptr, nullptr, nullptr,
              1, 1.0f, blockIdx.y * BM, blockIdx.x * BN);
}

// ---------------------------------------------------------------------------
// MMA flash attention, single fp16 (Q vs K; P vs V), compacted keys,
// index-based pad mask, 4-stage KV pipeline (cadence already correct via
// A_EMPTY in every non-issuing iteration).
// ---------------------------------------------------------------------------
#define AQ 128
#define AK 64
#define SM_Q 0
#define SM_ST0 18432
#define ST_STRIDE 18432       // K (9216) + V (9216)
#define OFF_K 0
#define OFF_V 9216
#define A_NSTG 4
#define ATTN_SMEM (SM_ST0 + A_NSTG * ST_STRIDE)   // 92160

__global__ __launch_bounds__(256, 1)
void attn_mma(const __half* __restrict__ Q16_, const __half* __restrict__ K16_,
              const __half* __restrict__ V16_, const int* __restrict__ cntp,
              __half* __restrict__ O16_)
{
    extern __shared__ char sm[];
    const uint32_t sb = smem_u32(sm);
    const int tid = threadIdx.x, lane = tid & 31, wid = tid >> 5;
    const int bh = blockIdx.y, b = bh >> 4, h = bh & 15;
    const int q0 = blockIdx.x * AQ;
    const size_t base = (size_t)bh * SEQ * HD;
    const int cntb = cntp[b];
    const int nt = (cntb + AK - 1) >> 6;

#define A_ISSUE(tile, stage) do { \
    uint32_t st_ = sb + SM_ST0 + (stage) * ST_STRIDE; \
    _Pragma("unroll") \
    for (int i_ = 0; i_ < 2; i_++) { \
        int idx_ = tid + i_ * 256, r_ = idx_ >> 3, c_ = idx_ & 7; \
        size_t go_ = base + (size_t)((tile) * AK + r_) * HD + c_ * 8; \
        uint32_t so_ = r_ * 144 + c_ * 16; \
        cpa16(st_ + OFF_K + so_, K16_ + go_); \
        cpa16(st_ + OFF_V + so_, V16_ + go_); \
    } \
    asm volatile("cp.async.commit_group;" ::: "memory"); \
} while (0)
#define A_EMPTY() asm volatile("cp.async.commit_group;" ::: "memory")

    {
#pragma unroll
        for (int i = 0; i < 4; i++) {
            int idx = tid + i * 256, r = idx >> 3, c = idx & 7;
            size_t go = base + (size_t)(q0 + r) * HD + c * 8;
            cpa16(sb + SM_Q + r * 144 + c * 16, Q16_ + go);
        }
        A_ISSUE(0, 0);   // group 0 includes Q
    }
    if (nt > 1) A_ISSUE(1, 1); else A_EMPTY();
    if (nt > 2) A_ISSUE(2, 2); else A_EMPTY();

    asm volatile("cp.async.wait_group 2;" ::: "memory");
    __syncthreads();

    uint32_t qf[4][4];
    {
        const int qrow = wid * 16 + (lane & 15);
        const int qc = (lane >> 4) * 8;
#pragma unroll
        for (int kf = 0; kf < 4; kf++)
            ldsm_x4(qf[kf], sb + SM_Q + qrow * 144 + (kf * 16 + qc) * 2);
    }

    float O[8][4];
#pragma unroll
    for (int i = 0; i < 8; i++)
#pragma unroll
        for (int j = 0; j < 4; j++) O[i][j] = 0.f;
    float mrun0 = -1e30f, mrun1 = -1e30f, lrun0 = 0.f, lrun1 = 0.f;

    const int kc2 = (lane & 3) * 2;
    const int krow = ((lane >> 4) & 1) * 8 + (lane & 7);
    const int kcol = ((lane >> 3) & 1) * 8;
    const int vrow = ((lane >> 3) & 1) * 8 + (lane & 7);
    const int vcol = ((lane >> 4) & 1) * 8;

    for (int t = 0; t < nt; t++) {
        const int stg = t & 3;
        if (t > 0) {
            asm volatile("cp.async.wait_group 2;" ::: "memory");
            __syncthreads();
        }
        if (t + 3 < nt) A_ISSUE(t + 3, (t + 3) & 3); else A_EMPTY();

        const uint32_t st = sb + SM_ST0 + stg * ST_STRIDE;
        const int limit = cntb - t * AK;   // keys >= limit are pad

        // ---- S = Q*K ----
        float S[8][4];
#pragma unroll
        for (int i = 0; i < 8; i++)
#pragma unroll
            for (int j = 0; j < 4; j++) S[i][j] = 0.f;

#pragma unroll
        for (int kf = 0; kf < 4; kf++) {
            uint32_t kb[4][4];
#pragma unroll
            for (int np = 0; np < 4; np++)
                ldsm_x4(kb[np], st + OFF_K + (np * 16 + krow) * 144 + (kf * 16 + kcol) * 2);
#pragma unroll
            for (int np = 0; np < 4; np++) {
                mma16816h(S[2 * np],     qf[kf], &kb[np][0]);
                mma16816h(S[2 * np + 1], qf[kf], &kb[np][2]);
            }
        }

        // ---- pad mask + online softmax ----
        float tmax0 = -1e30f, tmax1 = -1e30f;
#pragma unroll
        for (int nti = 0; nti < 8; nti++) {
            const int k = nti * 8 + kc2;
            if (k >= limit)     { S[nti][0] = -CUDART_INF_F; S[nti][2] = -CUDART_INF_F; }
            if (k + 1 >= limit) { S[nti][1] = -CUDART_INF_F; S[nti][3] = -CUDART_INF_F; }
            tmax0 = fmaxf(tmax0, fmaxf(S[nti][0], S[nti][1]));
            tmax1 = fmaxf(tmax1, fmaxf(S[nti][2], S[nti][3]));
        }
        tmax0 = fmaxf(tmax0, __shfl_xor_sync(0xFFFFFFFF, tmax0, 1));
        tmax0 = fmaxf(tmax0, __shfl_xor_sync(0xFFFFFFFF, tmax0, 2));
        tmax1 = fmaxf(tmax1, __shfl_xor_sync(0xFFFFFFFF, tmax1, 1));
        tmax1 = fmaxf(tmax1, __shfl_xor_sync(0xFFFFFFFF, tmax1, 2));

        const float mn0 = fmaxf(mrun0, tmax0);
        const float mn1 = fmaxf(mrun1, tmax1);
        const float sc0 = __expf(mrun0 - mn0);
        const float sc1 = __expf(mrun1 - mn1);
        mrun0 = mn0; mrun1 = mn1;

        float ts0 = 0.f, ts1 = 0.f;
        uint32_t ph[8][2];
#pragma unroll
        for (int nti = 0; nti < 8; nti++) {
            const float p0 = __expf(S[nti][0] - mn0);
            const float p1 = __expf(S[nti][1] - mn0);
            const float p2 = __expf(S[nti][2] - mn1);
            const float p3 = __expf(S[nti][3] - mn1);
            ts0 += p0 + p1; ts1 += p2 + p3;
            __half2 h01 = __floats2half2_rn(p0, p1);
            __half2 h23 = __floats2half2_rn(p2, p3);
            ph[nti][0] = *reinterpret_cast<uint32_t*>(&h01);
            ph[nti][1] = *reinterpret_cast<uint32_t*>(&h23);
        }
        ts0 += __shfl_xor_sync(0xFFFFFFFF, ts0, 1);
        ts0 += __shfl_xor_sync(0xFFFFFFFF, ts0, 2);
        ts1 += __shfl_xor_sync(0xFFFFFFFF, ts1, 1);
        ts1 += __shfl_xor_sync(0xFFFFFFFF, ts1, 2);
        lrun0 = lrun0 * sc0 + ts0;
        lrun1 = lrun1 * sc1 + ts1;
#pragma unroll
        for (int nti = 0; nti < 8; nti++) {
            O[nti][0] *= sc0; O[nti][1] *= sc0;
            O[nti][2] *= sc1; O[nti][3] *= sc1;
        }

        // ---- O += P*V ----
#pragma unroll
        for (int kf = 0; kf < 4; kf++) {
            uint32_t ah[4] = {ph[2 * kf][0], ph[2 * kf][1], ph[2 * kf + 1][0], ph[2 * kf + 1][1]};
            uint32_t vb[4][4];
#pragma unroll
            for (int np = 0; np < 4; np++)
                ldsm_x4t(vb[np], st + OFF_V + (kf * 16 + vrow) * 144 + (np * 16 + vcol) * 2);
#pragma unroll
            for (int np = 0; np < 4; np++) {
                mma16816h(O[2 * np],     ah, &vb[np][0]);
                mma16816h(O[2 * np + 1], ah, &vb[np][2]);
            }
        }
    }

    // ---- epilogue: single fp16 ----
    const float inv0 = 1.f / lrun0;
    const float inv1 = 1.f / lrun1;
    const int g = lane >> 2;
    const size_t row0 = (size_t)(b * SEQ + q0 + wid * 16 + g) * DIM + h * HD;
    const size_t row1 = row0 + (size_t)8 * DIM;
#pragma unroll
    for (int nti = 0; nti < 8; nti++) {
        const int col = nti * 8 + kc2;
        __half2 h0 = __floats2half2_rn(O[nti][0] * inv0, O[nti][1] * inv0);
        __half2 h1 = __floats2half2_rn(O[nti][2] * inv1, O[nti][3] * inv1);
        *(uint32_t*)&O16_[row0 + col] = *reinterpret_cast<uint32_t*>(&h0);
        *(uint32_t*)&O16_[row1 + col] = *reinterpret_cast<uint32_t*>(&h1);
    }
}

// ---------------------------------------------------------------------------
// Launch
// ---------------------------------------------------------------------------
extern "C" void kernel_launch(void* const* d_in, const int* in_sizes, int n_in,
                              void* d_out, int out_size)
{
    const float* x  = (const float*)d_in[0];
    const int* mask = (const int*)d_in[1];
    const float* Wq = (const float*)d_in[2];
    const float* bq = (const float*)d_in[3];
    const float* Wk = (const float*)d_in[4];
    const float* bk = (const float*)d_in[5];
    const float* Wv = (const float*)d_in[6];
    const float* bv = (const float*)d_in[7];
    const float* Wo = (const float*)d_in[8];
    const float* bo = (const float*)d_in[9];
    float* out = (float*)d_out;

    __half *pq16, *pk16, *pv16, *px16, *pw16, *po16;
    int *pgat, *pcnt;
    cudaGetSymbolAddress((void**)&pq16, g_q16);
    cudaGetSymbolAddress((void**)&pk16, g_k16);
    cudaGetSymbolAddress((void**)&pv16, g_v16);
    cudaGetSymbolAddress((void**)&px16, g_x16);
    cudaGetSymbolAddress((void**)&pw16, g_w16);
    cudaGetSymbolAddress((void**)&po16, g_o16);
    cudaGetSymbolAddress((void**)&pgat, g_gather);
    cudaGetSymbolAddress((void**)&pcnt, g_cnt);

    cudaFuncSetAttribute(gemm_qkv, cudaFuncAttributeMaxDynamicSharedMemorySize, GEMM_SMEM);
    cudaFuncSetAttribute(gemm_out, cudaFuncAttributeMaxDynamicSharedMemorySize, GEMM_SMEM);
    cudaFuncSetAttribute(attn_mma, cudaFuncAttributeMaxDynamicSharedMemorySize, ATTN_SMEM);

    round_all_kernel<<<2048, 256>>>(x, Wq, Wk, Wv, Wo, px16, pw16);
    compact_kernel<<<BATCH, 256>>>(mask, pgat, pcnt);

    dim3 qkvgrid(24, NROWS / BM);
    gemm_qkv<<<qkvgrid, GTHREADS, GEMM_SMEM>>>(px16, pw16, bq, bk, bv,
                                               pgat, pcnt, pq16, pk16, pv16);

    dim3 agrid(SEQ / AQ, BATCH * HEADS);
    attn_mma<<<agrid, 256, ATTN_SMEM>>>(pq16, pk16, pv16, pcnt, po16);

    dim3 ogrid(DIM / BN, NROWS / BM);
    gemm_out<<<ogrid, GTHREADS, GEMM_SMEM>>>(po16, pw16 + 3 * (size_t)DIM * DIM, bo, out);
}

// round 16
// speedup vs baseline: 1.0548x; 1.0548x over previous
#include <cuda_runtime.h>
#include <cuda_bf16.h>
#include <cuda_fp16.h>
#include <math_constants.h>
#include <cstdint>

// Problem constants
#define BATCH 4
#define SEQ   2048
#define DIM   1024
#define HEADS 16
#define HD    64
#define NROWS (BATCH * SEQ)   // 8192
#define QK_SCALE 0.125f

__device__ __forceinline__ uint32_t smem_u32(const void* p) {
    uint32_t a;
    asm("{ .reg .u64 t; cvta.to.shared.u64 t, %1; cvt.u32.u64 %0, t; }" : "=r"(a) : "l"(p));
    return a;
}
__device__ __forceinline__ void mma16816h(float* d, const uint32_t* a, const uint32_t* b) {
    asm volatile("mma.sync.aligned.m16n8k16.row.col.f32.f16.f16.f32 "
        "{%0,%1,%2,%3}, {%4,%5,%6,%7}, {%8,%9}, {%0,%1,%2,%3};"
        : "+f"(d[0]), "+f"(d[1]), "+f"(d[2]), "+f"(d[3])
        : "r"(a[0]), "r"(a[1]), "r"(a[2]), "r"(a[3]), "r"(b[0]), "r"(b[1]));
}
__device__ __forceinline__ void ldsm_x4(uint32_t* r, uint32_t addr) {
    asm volatile("ldmatrix.sync.aligned.m8n8.x4.shared.b16 {%0,%1,%2,%3}, [%4];"
        : "=r"(r[0]), "=r"(r[1]), "=r"(r[2]), "=r"(r[3]) : "r"(addr));
}
__device__ __forceinline__ void ldsm_x4t(uint32_t* r, uint32_t addr) {
    asm volatile("ldmatrix.sync.aligned.m8n8.x4.trans.shared.b16 {%0,%1,%2,%3}, [%4];"
        : "=r"(r[0]), "=r"(r[1]), "=r"(r[2]), "=r"(r[3]) : "r"(addr));
}
__device__ __forceinline__ void cpa16(uint32_t s, const void* g) {
    asm volatile("cp.async.cg.shared.global [%0], [%1], 16;" :: "r"(s), "l"(g));
}

// ---------------------------------------------------------------------------
// Scratch (all single fp16)
// ---------------------------------------------------------------------------
#define QKV_ELEMS (BATCH * HEADS * SEQ * HD)
__device__ __half g_q16[QKV_ELEMS];         // Q fp16 (pre-scaled)
__device__ __half g_k16[QKV_ELEMS];         // K fp16, compacted along S
__device__ __half g_v16[QKV_ELEMS];         // V fp16, compacted along S
__device__ __half g_x16[NROWS * DIM];       // x fp16
__device__ __half g_w16[4 * DIM * DIM];     // fp16-rounded weights
__device__ __half g_o16[NROWS * DIM];       // attn out fp16
__device__ int g_gather[BATCH * SEQ];
__device__ int g_cnt[BATCH];

// ---------------------------------------------------------------------------
// fp32 -> fp16 round: x and all four weights in ONE launch
// ---------------------------------------------------------------------------
struct h4 { __half v[4]; };

#define N4X (NROWS * DIM / 4)      // 2097152
#define N4W ((DIM * DIM) / 4)      // 262144

__global__ void round_all_kernel(const float* __restrict__ x,
                                 const float* __restrict__ w0, const float* __restrict__ w1,
                                 const float* __restrict__ w2, const float* __restrict__ w3,
                                 __half* __restrict__ dx, __half* __restrict__ dw)
{
    const int total = N4X + 4 * N4W;
    for (int i = blockIdx.x * blockDim.x + threadIdx.x; i < total;
         i += gridDim.x * blockDim.x) {
        const float* s;
        h4* d;
        int j;
        if (i < N4X) {
            s = x; d = (h4*)dx; j = i;
        } else {
            const int k = i - N4X;
            const int w = k / N4W;
            j = k - w * N4W;
            s = (w == 0) ? w0 : (w == 1) ? w1 : (w == 2) ? w2 : w3;
            d = (h4*)dw + (size_t)w * N4W;
        }
        float4 v = ((const float4*)s)[j];
        h4 h;
        h.v[0] = __float2half_rn(v.x); h.v[1] = __float2half_rn(v.y);
        h.v[2] = __float2half_rn(v.z); h.v[3] = __float2half_rn(v.w);
        d[j] = h;
    }
}

// ---------------------------------------------------------------------------
// Mask compaction: stable scan; gather list + count.
// ---------------------------------------------------------------------------
__global__ __launch_bounds__(256)
void compact_kernel(const int* __restrict__ mask,
                    int* __restrict__ gather, int* __restrict__ cnt)
{
    __shared__ int cnts[256];
    __shared__ int offs[256];
    const int b = blockIdx.x;
    const int t = threadIdx.x;
    const int* m = mask + b * SEQ;

    int c = 0;
#pragma unroll
    for (int j = 0; j < 8; j++) c += (m[t * 8 + j] == 0);
    cnts[t] = c;
    __syncthreads();
    if (t == 0) {
        int run = 0;
        for (int i = 0; i < 256; i++) { offs[i] = run; run += cnts[i]; }
        cnt[b] = run;
    }
    __syncthreads();
    int o = offs[t];
#pragma unroll
    for (int j = 0; j < 8; j++) {
        const int s = t * 8 + j;
        if (m[s] == 0) { gather[b * SEQ + o] = s; o++; }
    }
}

// ---------------------------------------------------------------------------
// fp16 single-term GEMM, 512 threads (16 warps, 4x4, 32x32 warp tiles),
// 4-stage cp.async pipeline, strict one-group-per-iteration cadence.
// ---------------------------------------------------------------------------
#define BM 128
#define BN 128
#define BK 32
#define NKC (DIM / BK)
#define TILE_SB (128 * 80)          // 10240 B
#define STAGE_SB (2 * TILE_SB)      // 20480 B: A, W
#define NSTG 4
#define GEMM_SMEM (NSTG * STAGE_SB) // 81920 B
#define GTHREADS 512

__device__ __forceinline__ void gemm_body(
    const __half* A16, const __half* W16,
    const float* bias, float* C, __half* Ch,
    const int* gather, const int* cntp,
    int mode, float scale, int row0, int col0)
{
    extern __shared__ char smraw[];
    const uint32_t smem_base = smem_u32(smraw);

    const int tid = threadIdx.x;
    const int lane = tid & 31;
    const int wid = tid >> 5;        // 0..15
    const int wm = wid & 3;
    const int wn = wid >> 2;

    int cntb = 0;
    if (mode == 2) {
        const int b = row0 >> 11;
        cntb = cntp[b];
        if ((row0 & (SEQ - 1)) >= cntb) return;
    }

    float acc[2][4][4];
#pragma unroll
    for (int i = 0; i < 2; i++)
#pragma unroll
        for (int j = 0; j < 4; j++)
#pragma unroll
            for (int r = 0; r < 4; r++) acc[i][j][r] = 0.f;

    const int r0l = tid >> 2;        // 0..127
    const int cu  = tid & 3;

    const uint4* ap;
    const uint4* wp;
    {
        int srcA;
        if (mode == 2) {
            const int n = row0 + r0l;
            const int b = n >> 11;
            int i = n & (SEQ - 1);
            if (i >= cntb) i = cntb - 1;
            srcA = (b << 11) + gather[(b << 11) + i];
        } else {
            srcA = row0 + r0l;
        }
        ap = (const uint4*)A16 + (size_t)srcA * 128 + cu;
        wp = (const uint4*)W16 + (size_t)(col0 + r0l) * 128 + cu;
    }

#define G_ISSUE(kc, buf) do { \
    uint32_t sb_ = smem_base + (buf) * STAGE_SB; \
    const uint32_t so_ = r0l * 80 + cu * 16; \
    cpa16(sb_ + 0 * TILE_SB + so_, ap + (kc) * 4); \
    cpa16(sb_ + 1 * TILE_SB + so_, wp + (kc) * 4); \
    asm volatile("cp.async.commit_group;" ::: "memory"); \
} while (0)
#define G_EMPTY() asm volatile("cp.async.commit_group;" ::: "memory")

    G_ISSUE(0, 0);
    G_ISSUE(1, 1);
    G_ISSUE(2, 2);

    for (int kc = 0; kc < NKC; kc++) {
        const int buf = kc & 3;
        asm volatile("cp.async.wait_group 2;" ::: "memory");
        __syncthreads();
        if (kc + 3 < NKC) G_ISSUE(kc + 3, (kc + 3) & 3);
        else              G_EMPTY();

        const uint32_t sb = smem_base + buf * STAGE_SB;
#pragma unroll
        for (int s = 0; s < 2; s++) {
            uint32_t a_f[2][4];
            const uint32_t acol = s * 32 + ((lane >> 4) << 4);
#pragma unroll
            for (int mt = 0; mt < 2; mt++) {
                const int r = wm * 32 + mt * 16 + (lane & 15);
                ldsm_x4(a_f[mt], sb + r * 80 + acol);
            }
            uint32_t wf[4][2];
            const int mat = lane >> 3;
            const int mr = lane & 7;
            const uint32_t bcol = s * 32 + ((mat & 1) << 4);
#pragma unroll
            for (int np = 0; np < 2; np++) {
                const int n = wn * 32 + (np * 2 + (mat >> 1)) * 8 + mr;
                uint32_t addr = sb + TILE_SB + n * 80 + bcol;
                uint32_t q[4];
                ldsm_x4(q, addr);
                wf[np * 2][0] = q[0]; wf[np * 2][1] = q[1];
                wf[np * 2 + 1][0] = q[2]; wf[np * 2 + 1][1] = q[3];
            }
#pragma unroll
            for (int mt = 0; mt < 2; mt++)
#pragma unroll
                for (int nt = 0; nt < 4; nt++)
                    mma16816h(acc[mt][nt], a_f[mt], wf[nt]);
        }
    }

    const int g = lane >> 2;
    const int tg2 = (lane & 3) * 2;
#pragma unroll
    for (int mt = 0; mt < 2; mt++) {
#pragma unroll
        for (int hh = 0; hh < 2; hh++) {
            const int n = row0 + wm * 32 + mt * 16 + g + hh * 8;
            if (mode == 1) {
#pragma unroll
                for (int nt = 0; nt < 4; nt++) {
                    const int m = col0 + wn * 32 + nt * 8 + tg2;
                    float2 w;
                    w.x = acc[mt][nt][hh * 2 + 0] + bias[m];
                    w.y = acc[mt][nt][hh * 2 + 1] + bias[m + 1];
                    *(float2*)&C[(size_t)n * DIM + m] = w;
                }
            } else {
                const int b = n >> 11;
                const int sq = n & (SEQ - 1);
                if (mode == 2 && sq >= cntb) continue;
#pragma unroll
                for (int nt = 0; nt < 4; nt++) {
                    const int m = col0 + wn * 32 + nt * 8 + tg2;
                    const float v0 = (acc[mt][nt][hh * 2 + 0] + bias[m]) * scale;
                    const float v1 = (acc[mt][nt][hh * 2 + 1] + bias[m + 1]) * scale;
                    const int h = m >> 6;
                    const int hd = m & (HD - 1);
                    const size_t o = (((size_t)(b * HEADS + h) * SEQ) + sq) * HD + hd;
                    __half2 hv = __floats2half2_rn(v0, v1);
                    *(uint32_t*)&Ch[o] = *reinterpret_cast<uint32_t*>(&hv);
                }
            }
        }
    }
}

// Fused Q/K/V projection: grid (24, 64)
__global__ __launch_bounds__(GTHREADS, 1)
void gemm_qkv(const __half* __restrict__ x16, const __half* __restrict__ w16,
              const float* __restrict__ bq, const float* __restrict__ bk,
              const float* __restrict__ bv,
              const int* __restrict__ gather, const int* __restrict__ cnt,
              __half* __restrict__ q16, __half* __restrict__ k16,
              __half* __restrict__ v16)
{
    const int w = blockIdx.x >> 3;
    const int col0 = (blockIdx.x & 7) * BN;
    const int row0 = blockIdx.y * BM;
    const int NW = DIM * DIM;
    const float* bias = (w == 0) ? bq : (w == 1) ? bk : bv;
    __half* Ch = (w == 0) ? q16 : (w == 1) ? k16 : v16;
    const float scale = (w == 0) ? QK_SCALE : 1.0f;
    const int mode = (w == 0) ? 0 : 2;
    gemm_body(x16, w16 + (size_t)w * NW, bias, nullptr, Ch,
              gather, cnt, mode, scale, row0, col0);
}

__global__ __launch_bounds__(GTHREADS, 1)
void gemm_out(const __half* __restrict__ o16, const __half* __restrict__ w16,
              const float* __restrict__ bias, float* __restrict__ out)
{
    gemm_body(o16, w16, bias, out, nullptr, nullptr, nullptr,
              1, 1.0f, blockIdx.y * BM, blockIdx.x * BN);
}

// ---------------------------------------------------------------------------
// MMA flash attention, single fp16, compacted keys, 4-stage KV pipeline.
// 2 CTAs/SM (launch_bounds cap 128 regs); packed P reuses S registers.
// ---------------------------------------------------------------------------
#define AQ 128
#define AK 64
#define SM_Q 0
#define SM_ST0 18432
#define ST_STRIDE 18432       // K (9216) + V (9216)
#define OFF_K 0
#define OFF_V 9216
#define A_NSTG 4
#define ATTN_SMEM (SM_ST0 + A_NSTG * ST_STRIDE)   // 92160 (x2 CTAs = 184320 <= 228KB)

__global__ __launch_bounds__(256, 2)
void attn_mma(const __half* __restrict__ Q16_, const __half* __restrict__ K16_,
              const __half* __restrict__ V16_, const int* __restrict__ cntp,
              __half* __restrict__ O16_)
{
    extern __shared__ char sm[];
    const uint32_t sb = smem_u32(sm);
    const int tid = threadIdx.x, lane = tid & 31, wid = tid >> 5;
    const int bh = blockIdx.y, b = bh >> 4, h = bh & 15;
    const int q0 = blockIdx.x * AQ;
    const size_t base = (size_t)bh * SEQ * HD;
    const int cntb = cntp[b];
    const int nt = (cntb + AK - 1) >> 6;

#define A_ISSUE(tile, stage) do { \
    uint32_t st_ = sb + SM_ST0 + (stage) * ST_STRIDE; \
    _Pragma("unroll") \
    for (int i_ = 0; i_ < 2; i_++) { \
        int idx_ = tid + i_ * 256, r_ = idx_ >> 3, c_ = idx_ & 7; \
        size_t go_ = base + (size_t)((tile) * AK + r_) * HD + c_ * 8; \
        uint32_t so_ = r_ * 144 + c_ * 16; \
        cpa16(st_ + OFF_K + so_, K16_ + go_); \
        cpa16(st_ + OFF_V + so_, V16_ + go_); \
    } \
    asm volatile("cp.async.commit_group;" ::: "memory"); \
} while (0)
#define A_EMPTY() asm volatile("cp.async.commit_group;" ::: "memory")

    {
#pragma unroll
        for (int i = 0; i < 4; i++) {
            int idx = tid + i * 256, r = idx >> 3, c = idx & 7;
            size_t go = base + (size_t)(q0 + r) * HD + c * 8;
            cpa16(sb + SM_Q + r * 144 + c * 16, Q16_ + go);
        }
        A_ISSUE(0, 0);   // group 0 includes Q
    }
    if (nt > 1) A_ISSUE(1, 1); else A_EMPTY();
    if (nt > 2) A_ISSUE(2, 2); else A_EMPTY();

    asm volatile("cp.async.wait_group 2;" ::: "memory");
    __syncthreads();

    uint32_t qf[4][4];
    {
        const int qrow = wid * 16 + (lane & 15);
        const int qc = (lane >> 4) * 8;
#pragma unroll
        for (int kf = 0; kf < 4; kf++)
            ldsm_x4(qf[kf], sb + SM_Q + qrow * 144 + (kf * 16 + qc) * 2);
    }

    float O[8][4];
#pragma unroll
    for (int i = 0; i < 8; i++)
#pragma unroll
        for (int j = 0; j < 4; j++) O[i][j] = 0.f;
    float mrun0 = -1e30f, mrun1 = -1e30f, lrun0 = 0.f, lrun1 = 0.f;

    const int kc2 = (lane & 3) * 2;
    const int krow = ((lane >> 4) & 1) * 8 + (lane & 7);
    const int kcol = ((lane >> 3) & 1) * 8;
    const int vrow = ((lane >> 3) & 1) * 8 + (lane & 7);
    const int vcol = ((lane >> 4) & 1) * 8;

    for (int t = 0; t < nt; t++) {
        const int stg = t & 3;
        if (t > 0) {
            asm volatile("cp.async.wait_group 2;" ::: "memory");
            __syncthreads();
        }
        if (t + 3 < nt) A_ISSUE(t + 3, (t + 3) & 3); else A_EMPTY();

        const uint32_t st = sb + SM_ST0 + stg * ST_STRIDE;
        const int limit = cntb - t * AK;   // keys >= limit are pad

        // ---- S = Q*K ----
        float S[8][4];
#pragma unroll
        for (int i = 0; i < 8; i++)
#pragma unroll
            for (int j = 0; j < 4; j++) S[i][j] = 0.f;

#pragma unroll
        for (int kf = 0; kf < 4; kf++) {
            uint32_t kb[4][4];
#pragma unroll
            for (int np = 0; np < 4; np++)
                ldsm_x4(kb[np], st + OFF_K + (np * 16 + krow) * 144 + (kf * 16 + kcol) * 2);
#pragma unroll
            for (int np = 0; np < 4; np++) {
                mma16816h(S[2 * np],     qf[kf], &kb[np][0]);
                mma16816h(S[2 * np + 1], qf[kf], &kb[np][2]);
            }
        }

        // ---- pad mask + online softmax ----
        float tmax0 = -1e30f, tmax1 = -1e30f;
#pragma unroll
        for (int nti = 0; nti < 8; nti++) {
            const int k = nti * 8 + kc2;
            if (k >= limit)     { S[nti][0] = -CUDART_INF_F; S[nti][2] = -CUDART_INF_F; }
            if (k + 1 >= limit) { S[nti][1] = -CUDART_INF_F; S[nti][3] = -CUDART_INF_F; }
            tmax0 = fmaxf(tmax0, fmaxf(S[nti][0], S[nti][1]));
            tmax1 = fmaxf(tmax1, fmaxf(S[nti][2], S[nti][3]));
        }
        tmax0 = fmaxf(tmax0, __shfl_xor_sync(0xFFFFFFFF, tmax0, 1));
        tmax0 = fmaxf(tmax0, __shfl_xor_sync(0xFFFFFFFF, tmax0, 2));
        tmax1 = fmaxf(tmax1, __shfl_xor_sync(0xFFFFFFFF, tmax1, 1));
        tmax1 = fmaxf(tmax1, __shfl_xor_sync(0xFFFFFFFF, tmax1, 2));

        const float mn0 = fmaxf(mrun0, tmax0);
        const float mn1 = fmaxf(mrun1, tmax1);
        const float sc0 = __expf(mrun0 - mn0);
        const float sc1 = __expf(mrun1 - mn1);
        mrun0 = mn0; mrun1 = mn1;

        float ts0 = 0.f, ts1 = 0.f;
        // pack P into the S registers (reuse: S[nti][0]=bits(p0,p1), S[nti][1]=bits(p2,p3))
#pragma unroll
        for (int nti = 0; nti < 8; nti++) {
            const float p0 = __expf(S[nti][0] - mn0);
            const float p1 = __expf(S[nti][1] - mn0);
            const float p2 = __expf(S[nti][2] - mn1);
            const float p3 = __expf(S[nti][3] - mn1);
            ts0 += p0 + p1; ts1 += p2 + p3;
            __half2 h01 = __floats2half2_rn(p0, p1);
            __half2 h23 = __floats2half2_rn(p2, p3);
            S[nti][0] = __uint_as_float(*reinterpret_cast<uint32_t*>(&h01));
            S[nti][1] = __uint_as_float(*reinterpret_cast<uint32_t*>(&h23));
        }
        ts0 += __shfl_xor_sync(0xFFFFFFFF, ts0, 1);
        ts0 += __shfl_xor_sync(0xFFFFFFFF, ts0, 2);
        ts1 += __shfl_xor_sync(0xFFFFFFFF, ts1, 1);
        ts1 += __shfl_xor_sync(0xFFFFFFFF, ts1, 2);
        lrun0 = lrun0 * sc0 + ts0;
        lrun1 = lrun1 * sc1 + ts1;
#pragma unroll
        for (int nti = 0; nti < 8; nti++) {
            O[nti][0] *= sc0; O[nti][1] *= sc0;
            O[nti][2] *= sc1; O[nti][3] *= sc1;
        }

        // ---- O += P*V ----
#pragma unroll
        for (int kf = 0; kf < 4; kf++) {
            uint32_t ah[4] = {__float_as_uint(S[2 * kf][0]), __float_as_uint(S[2 * kf][1]),
                              __float_as_uint(S[2 * kf + 1][0]), __float_as_uint(S[2 * kf + 1][1])};
            uint32_t vb[4][4];
#pragma unroll
            for (int np = 0; np < 4; np++)
                ldsm_x4t(vb[np], st + OFF_V + (kf * 16 + vrow) * 144 + (np * 16 + vcol) * 2);
#pragma unroll
            for (int np = 0; np < 4; np++) {
                mma16816h(O[2 * np],     ah, &vb[np][0]);
                mma16816h(O[2 * np + 1], ah, &vb[np][2]);
            }
        }
    }

    // ---- epilogue: single fp16 ----
    const float inv0 = 1.f / lrun0;
    const float inv1 = 1.f / lrun1;
    const int g = lane >> 2;
    const size_t row0 = (size_t)(b * SEQ + q0 + wid * 16 + g) * DIM + h * HD;
    const size_t row1 = row0 + (size_t)8 * DIM;
#pragma unroll
    for (int nti = 0; nti < 8; nti++) {
        const int col = nti * 8 + kc2;
        __half2 h0 = __floats2half2_rn(O[nti][0] * inv0, O[nti][1] * inv0);
        __half2 h1 = __floats2half2_rn(O[nti][2] * inv1, O[nti][3] * inv1);
        *(uint32_t*)&O16_[row0 + col] = *reinterpret_cast<uint32_t*>(&h0);
        *(uint32_t*)&O16_[row1 + col] = *reinterpret_cast<uint32_t*>(&h1);
    }
}

// ---------------------------------------------------------------------------
// Launch
// ---------------------------------------------------------------------------
extern "C" void kernel_launch(void* const* d_in, const int* in_sizes, int n_in,
                              void* d_out, int out_size)
{
    const float* x  = (const float*)d_in[0];
    const int* mask = (const int*)d_in[1];
    const float* Wq = (const float*)d_in[2];
    const float* bq = (const float*)d_in[3];
    const float* Wk = (const float*)d_in[4];
    const float* bk = (const float*)d_in[5];
    const float* Wv = (const float*)d_in[6];
    const float* bv = (const float*)d_in[7];
    const float* Wo = (const float*)d_in[8];
    const float* bo = (const float*)d_in[9];
    float* out = (float*)d_out;

    __half *pq16, *pk16, *pv16, *px16, *pw16, *po16;
    int *pgat, *pcnt;
    cudaGetSymbolAddress((void**)&pq16, g_q16);
    cudaGetSymbolAddress((void**)&pk16, g_k16);
    cudaGetSymbolAddress((void**)&pv16, g_v16);
    cudaGetSymbolAddress((void**)&px16, g_x16);
    cudaGetSymbolAddress((void**)&pw16, g_w16);
    cudaGetSymbolAddress((void**)&po16, g_o16);
    cudaGetSymbolAddress((void**)&pgat, g_gather);
    cudaGetSymbolAddress((void**)&pcnt, g_cnt);

    cudaFuncSetAttribute(gemm_qkv, cudaFuncAttributeMaxDynamicSharedMemorySize, GEMM_SMEM);
    cudaFuncSetAttribute(gemm_out, cudaFuncAttributeMaxDynamicSharedMemorySize, GEMM_SMEM);
    cudaFuncSetAttribute(attn_mma, cudaFuncAttributeMaxDynamicSharedMemorySize, ATTN_SMEM);

    round_all_kernel<<<2048, 256>>>(x, Wq, Wk, Wv, Wo, px16, pw16);
    compact_kernel<<<BATCH, 256>>>(mask, pgat, pcnt);

    dim3 qkvgrid(24, NROWS / BM);
    gemm_qkv<<<qkvgrid, GTHREADS, GEMM_SMEM>>>(px16, pw16, bq, bk, bv,
                                               pgat, pcnt, pq16, pk16, pv16);

    dim3 agrid(SEQ / AQ, BATCH * HEADS);
    attn_mma<<<agrid, 256, ATTN_SMEM>>>(pq16, pk16, pv16, pcnt, po16);

    dim3 ogrid(DIM / BN, NROWS / BM);
    gemm_out<<<ogrid, GTHREADS, GEMM_SMEM>>>(po16, pw16 + 3 * (size_t)DIM * DIM, bo, out);
}